// round 4
// baseline (speedup 1.0000x reference)
#include <cuda_runtime.h>
#include <math.h>

#define D        64
#define N_USERS  100000
#define N_ITEMS  50000
#define N_ENT    180000
#define N_UN     150000
#define E_KG     1500000
#define E_USR    1000000
#define E_MAT    1500000
#define EMASK    0xFFFFF
#define NROWS_ALL (N_ENT + N_UN + N_ITEMS + N_USERS)   // 480000

// ---------------- static scratch (no allocations allowed) ----------------
__device__ int g_cnt_e[N_ENT],   g_off_e[N_ENT];
__device__ int g_cnt_u[N_UN],    g_off_u[N_UN];
__device__ int g_cnt_ic[N_ITEMS],g_off_ic[N_ITEMS];
__device__ int g_cnt_ur[N_USERS],g_off_ur[N_USERS];
__device__ int g_cursor[4];
__device__ int g_rank_kg[E_KG], g_rank_u[E_USR], g_rank_mc[E_MAT], g_rank_mr[E_MAT];
__device__ int g_bkt_e[E_KG],   g_bkt_u[E_USR],  g_bkt_ic[E_MAT],  g_bkt_ur[E_MAT];
__device__ float g_iu[(size_t)N_ITEMS * D];
__device__ float g_ui[(size_t)N_USERS * D];

// ---------------- zero histograms + cursors ----------------
__global__ void zero_counts(int* a, int na, int* b, int nb,
                            int* c, int nc, int* d, int nd, int* cur)
{
    int i = blockIdx.x * blockDim.x + threadIdx.x;
    int stride = gridDim.x * blockDim.x;
    for (int k = i; k < na; k += stride) a[k] = 0;
    for (int k = i; k < nb; k += stride) b[k] = 0;
    for (int k = i; k < nc; k += stride) c[k] = 0;
    for (int k = i; k < nd; k += stride) d[k] = 0;
    if (i < 4) cur[i] = 0;
}

// ---------------- merged histogram, ILP x4 ----------------
// CH is a multiple of 256 and grid = CH/256, so gid < CH always: the four
// chunks [u*CH, (u+1)*CH) are disjoint (this was the R3 double-count bug).
__global__ __launch_bounds__(256) void hist_all(
    const int* __restrict__ ei,  const int* __restrict__ uei,
    const int* __restrict__ mr,  const int* __restrict__ mc,
    int* ce, int* rkg, int* cu, int* ru,
    int* cur_c, int* rmr, int* cic, int* rmc,
    int E, int UE, int M, int CH)
{
    int gid = blockIdx.x * blockDim.x + threadIdx.x;
    int W = E + UE + M;
    #pragma unroll
    for (int u = 0; u < 4; u++) {
        int idx = gid + u * CH;
        if (idx >= W) continue;
        if (idx < E) {
            rkg[idx] = atomicAdd(ce + ei[idx], 1);
        } else if (idx < E + UE) {
            int k = idx - E;
            ru[k] = atomicAdd(cu + uei[k], 1);
        } else {
            int k = idx - E - UE;
            rmr[k] = atomicAdd(cur_c + mr[k], 1);
            rmc[k] = atomicAdd(cic + mc[k], 1);
        }
    }
}

// ---------------- merged offsets: 4 segments, block-partitioned -------------
#define NB_E  ((N_ENT   + 255) / 256)
#define NB_U  ((N_UN    + 255) / 256)
#define NB_IC ((N_ITEMS + 255) / 256)
#define NB_UR ((N_USERS + 255) / 256)

__global__ __launch_bounds__(256) void offsets_all(
    const int* __restrict__ ce, int* oe,
    const int* __restrict__ cu, int* ou,
    const int* __restrict__ cic, int* oic,
    const int* __restrict__ cur_c, int* our,
    int* cursor)
{
    const int* cnt; int* off; int* cur; int n; int lb;
    int b = blockIdx.x;
    if (b < NB_E)                    { cnt = ce;    off = oe;  cur = cursor + 0; n = N_ENT;   lb = b; }
    else if (b < NB_E + NB_U)        { cnt = cu;    off = ou;  cur = cursor + 1; n = N_UN;    lb = b - NB_E; }
    else if (b < NB_E + NB_U + NB_IC){ cnt = cic;   off = oic; cur = cursor + 2; n = N_ITEMS; lb = b - NB_E - NB_U; }
    else                             { cnt = cur_c; off = our; cur = cursor + 3; n = N_USERS; lb = b - NB_E - NB_U - NB_IC; }

    __shared__ int wsum[8];
    __shared__ int bbase;
    int i = lb * 256 + threadIdx.x;
    int lane = threadIdx.x & 31, w = threadIdx.x >> 5;
    int v = (i < n) ? cnt[i] : 0;
    int x = v;
    #pragma unroll
    for (int d = 1; d < 32; d <<= 1) {
        int y = __shfl_up_sync(0xFFFFFFFFu, x, d);
        if (lane >= d) x += y;
    }
    if (lane == 31) wsum[w] = x;
    __syncthreads();
    if (threadIdx.x == 0) {
        int run = 0;
        #pragma unroll
        for (int k = 0; k < 8; k++) { int t = wsum[k]; wsum[k] = run; run += t; }
        bbase = atomicAdd(cur, run);
    }
    __syncthreads();
    if (i < n) off[i] = bbase + wsum[w] + (x - v);
}

// ---------------- merged fill, ILP x4 (same disjoint-chunk scheme) ----------
__global__ __launch_bounds__(256) void fill_all(
    const int* __restrict__ ei,  const int* __restrict__ et,
    const int* __restrict__ uei, const int* __restrict__ uet,
    const int* __restrict__ mr,  const int* __restrict__ mc,
    const int* __restrict__ oe,  const int* __restrict__ rkg, int* be,
    const int* __restrict__ ou,  const int* __restrict__ ru,  int* bu,
    const int* __restrict__ our, const int* __restrict__ rmr, int* bur,
    const int* __restrict__ oic, const int* __restrict__ rmc, int* bic,
    int E, int UE, int M, int CH)
{
    int gid = blockIdx.x * blockDim.x + threadIdx.x;
    int W = E + UE + M;
    #pragma unroll
    for (int u = 0; u < 4; u++) {
        int idx = gid + u * CH;
        if (idx >= W) continue;
        if (idx < E) {
            int packed = ei[E + idx] | (et[idx] << 20);       // tail | type
            be[oe[ei[idx]] + rkg[idx]] = packed;
        } else if (idx < E + UE) {
            int k = idx - E;
            int packed = uei[UE + k] | (uet[k] << 20);
            bu[ou[uei[k]] + ru[k]] = packed;
        } else {
            int k = idx - E - UE;
            int r = mr[k], c = mc[k];
            bur[our[r] + rmr[k]] = c;    // u_i: src = entity idx (type 0)
            bic[oic[c] + rmc[k]] = r;    // i_u: src = user idx   (type 0)
        }
    }
}

// ---------------- merged gather: warp per destination row -------------------
__global__ __launch_bounds__(256) void gather_all(
    const float* __restrict__ entity_emb, const float* __restrict__ user_emb,
    const float* __restrict__ wgt,
    const int* __restrict__ be,  const int* __restrict__ oe,  const int* __restrict__ ce,
    const int* __restrict__ bu,  const int* __restrict__ ou,  const int* __restrict__ cu,
    const int* __restrict__ bic, const int* __restrict__ oic, const int* __restrict__ cic,
    const int* __restrict__ bur, const int* __restrict__ our, const int* __restrict__ cur_c,
    float* __restrict__ ent_out, float* __restrict__ usr_out,
    float* __restrict__ iu, float* __restrict__ ui)
{
    __shared__ float2 sW[32 * 32];
    for (int i = threadIdx.x; i < 1024; i += 256)
        sW[i] = ((const float2*)wgt)[i];
    __syncthreads();

    int gid = blockIdx.x * 256 + threadIdx.x;
    int r = gid >> 5;
    int lane = gid & 31;
    if (r >= NROWS_ALL) return;

    const float* emb; const int* bkt; int o; int n; float* out; int lr;
    if (r < N_ENT) {
        lr = r;
        emb = entity_emb; bkt = be;
        o = __ldg(oe + lr); n = __ldg(ce + lr); out = ent_out;
    } else if (r < N_ENT + N_UN) {
        lr = r - N_ENT;
        emb = user_emb; bkt = bu;
        o = __ldg(ou + lr); n = __ldg(cu + lr); out = usr_out;
    } else if (r < N_ENT + N_UN + N_ITEMS) {
        lr = r - N_ENT - N_UN;
        emb = user_emb; bkt = bic;
        o = __ldg(oic + lr); n = __ldg(cic + lr); out = iu;
    } else {
        lr = r - N_ENT - N_UN - N_ITEMS;
        emb = entity_emb; bkt = bur;
        o = __ldg(our + lr); n = __ldg(cur_c + lr); out = ui;
    }

    float2 a0 = make_float2(0.f, 0.f), a1 = make_float2(0.f, 0.f);
    int j = 0;
    for (; j + 1 < n; j += 2) {
        int p0 = __ldg(bkt + o + j);
        int p1 = __ldg(bkt + o + j + 1);
        float2 v0 = __ldg((const float2*)(emb + ((size_t)(p0 & EMASK) << 6)) + lane);
        float2 v1 = __ldg((const float2*)(emb + ((size_t)(p1 & EMASK) << 6)) + lane);
        float2 wa = sW[(((unsigned)p0 >> 20) << 5) + lane];
        float2 wb = sW[(((unsigned)p1 >> 20) << 5) + lane];
        a0.x = fmaf(v0.x, wa.x, a0.x); a0.y = fmaf(v0.y, wa.y, a0.y);
        a1.x = fmaf(v1.x, wb.x, a1.x); a1.y = fmaf(v1.y, wb.y, a1.y);
    }
    if (j < n) {
        int p0 = __ldg(bkt + o + j);
        float2 v0 = __ldg((const float2*)(emb + ((size_t)(p0 & EMASK) << 6)) + lane);
        float2 wa = sW[(((unsigned)p0 >> 20) << 5) + lane];
        a0.x = fmaf(v0.x, wa.x, a0.x); a0.y = fmaf(v0.y, wa.y, a0.y);
    }
    float inv = 1.f / fmaxf((float)n, 1.f);
    float2 res = make_float2((a0.x + a1.x) * inv, (a0.y + a1.y) * inv);
    *((float2*)(out + ((size_t)lr << 6)) + lane) = res;
}

// ---------------- merged gated fusion (two jobs, one grid) ------------------
// out = sig(A @ Ga^T + B @ Gb^T) * A + (1 - sig) * B   (in place over A rows)
#define FUS_BLOCKS_ITEMS 592
#define FUS_BLOCKS_USERS 1184
#define FUS_BLOCKS (FUS_BLOCKS_ITEMS + FUS_BLOCKS_USERS)

__global__ __launch_bounds__(256) void fusion2(
    const float* __restrict__ A0, const float* __restrict__ B0,
    const float* __restrict__ Ga0, const float* __restrict__ Gb0, float* __restrict__ out0, int n0,
    const float* __restrict__ A1, const float* __restrict__ B1,
    const float* __restrict__ Ga1, const float* __restrict__ Gb1, float* __restrict__ out1, int n1)
{
    const float *A, *B, *Ga, *Gb; float* out; int nrows, bid, nblk;
    if (blockIdx.x < FUS_BLOCKS_ITEMS) {
        A = A0; B = B0; Ga = Ga0; Gb = Gb0; out = out0; nrows = n0;
        bid = blockIdx.x; nblk = FUS_BLOCKS_ITEMS;
    } else {
        A = A1; B = B1; Ga = Ga1; Gb = Gb1; out = out1; nrows = n1;
        bid = blockIdx.x - FUS_BLOCKS_ITEMS; nblk = FUS_BLOCKS_USERS;
    }

    __shared__ float sGa[64 * 65];
    __shared__ float sGb[64 * 65];
    __shared__ float sA[16][64];
    __shared__ float sB[16][64];

    int t = threadIdx.x;
    for (int idx = t; idx < 4096; idx += 256) {
        int j = idx >> 6, k = idx & 63;
        sGa[k * 65 + j] = Ga[idx];
        sGb[k * 65 + j] = Gb[idx];
    }
    __syncthreads();

    int ntiles = (nrows + 15) >> 4;
    for (int tile = bid; tile < ntiles; tile += nblk) {
        int row0 = tile << 4;
        for (int idx = t; idx < 1024; idx += 256) {
            int r = idx >> 6, k = idx & 63;
            int row = row0 + r;
            float a = 0.f, b = 0.f;
            if (row < nrows) {
                a = A[(size_t)row * D + k];
                b = B[(size_t)row * D + k];
            }
            sA[r][k] = a;
            sB[r][k] = b;
        }
        __syncthreads();

        int j0 = t & 31;
        int r0 = t >> 5;
        float aa00 = 0.f, aa01 = 0.f, aa10 = 0.f, aa11 = 0.f;
        float bb00 = 0.f, bb01 = 0.f, bb10 = 0.f, bb11 = 0.f;
        #pragma unroll
        for (int k = 0; k < 64; k++) {
            float ga0 = sGa[k * 65 + j0];
            float ga1 = sGa[k * 65 + j0 + 32];
            float gb0 = sGb[k * 65 + j0];
            float gb1 = sGb[k * 65 + j0 + 32];
            float a0 = sA[r0][k], a1 = sA[r0 + 8][k];
            float b0 = sB[r0][k], b1 = sB[r0 + 8][k];
            aa00 = fmaf(a0, ga0, aa00); aa01 = fmaf(a0, ga1, aa01);
            aa10 = fmaf(a1, ga0, aa10); aa11 = fmaf(a1, ga1, aa11);
            bb00 = fmaf(b0, gb0, bb00); bb01 = fmaf(b0, gb1, bb01);
            bb10 = fmaf(b1, gb0, bb10); bb11 = fmaf(b1, gb1, bb11);
        }

        #pragma unroll
        for (int q = 0; q < 4; q++) {
            int rr = r0 + ((q >> 1) ? 8 : 0);
            int jj = j0 + ((q & 1) ? 32 : 0);
            float x;
            if (q == 0) x = aa00 + bb00;
            else if (q == 1) x = aa01 + bb01;
            else if (q == 2) x = aa10 + bb10;
            else x = aa11 + bb11;
            int row = row0 + rr;
            if (row < nrows) {
                float g = 1.0f / (1.0f + __expf(-x));
                out[(size_t)row * D + jj] = g * sA[rr][jj] + (1.0f - g) * sB[rr][jj];
            }
        }
        __syncthreads();
    }
}

extern "C" void kernel_launch(void* const* d_in, const int* in_sizes, int n_in,
                              void* d_out, int out_size)
{
    const float* entity_emb = (const float*)d_in[0];
    const float* user_emb   = (const float*)d_in[1];
    const float* weight     = (const float*)d_in[2];
    const float* gate1_w    = (const float*)d_in[3];
    const float* gate2_w    = (const float*)d_in[4];
    const float* gate3_w    = (const float*)d_in[5];
    const int* edge_index      = (const int*)d_in[6];
    const int* edge_type       = (const int*)d_in[7];
    const int* user_edge_index = (const int*)d_in[8];
    const int* user_edge_type  = (const int*)d_in[9];
    const int* mat_row         = (const int*)d_in[10];
    const int* mat_col         = (const int*)d_in[11];

    int E  = in_sizes[7];
    int UE = in_sizes[9];
    int M  = in_sizes[10];

    float* out     = (float*)d_out;
    float* ent_out = out;
    float* usr_out = out + (size_t)N_ENT * D;

    int *p_ce, *p_cu, *p_cic, *p_cur, *p_oe, *p_ou, *p_oic, *p_our, *p_cursor;
    int *p_rkg, *p_ru, *p_rmc, *p_rmr, *p_be, *p_bu, *p_bic, *p_bur;
    float *p_iu, *p_ui;
    cudaGetSymbolAddress((void**)&p_ce,  g_cnt_e);
    cudaGetSymbolAddress((void**)&p_cu,  g_cnt_u);
    cudaGetSymbolAddress((void**)&p_cic, g_cnt_ic);
    cudaGetSymbolAddress((void**)&p_cur, g_cnt_ur);
    cudaGetSymbolAddress((void**)&p_oe,  g_off_e);
    cudaGetSymbolAddress((void**)&p_ou,  g_off_u);
    cudaGetSymbolAddress((void**)&p_oic, g_off_ic);
    cudaGetSymbolAddress((void**)&p_our, g_off_ur);
    cudaGetSymbolAddress((void**)&p_cursor, g_cursor);
    cudaGetSymbolAddress((void**)&p_rkg, g_rank_kg);
    cudaGetSymbolAddress((void**)&p_ru,  g_rank_u);
    cudaGetSymbolAddress((void**)&p_rmc, g_rank_mc);
    cudaGetSymbolAddress((void**)&p_rmr, g_rank_mr);
    cudaGetSymbolAddress((void**)&p_be,  g_bkt_e);
    cudaGetSymbolAddress((void**)&p_bu,  g_bkt_u);
    cudaGetSymbolAddress((void**)&p_bic, g_bkt_ic);
    cudaGetSymbolAddress((void**)&p_bur, g_bkt_ur);
    cudaGetSymbolAddress((void**)&p_iu,  g_iu);
    cudaGetSymbolAddress((void**)&p_ui,  g_ui);

    // 1) zero histograms + cursors
    zero_counts<<<512, 256>>>(p_ce, N_ENT, p_cu, N_UN, p_cic, N_ITEMS,
                              p_cur, N_USERS, p_cursor);

    // 2) merged histogram (ILP x4) — CH 256-aligned, grid exactly CH/256
    int W = E + UE + M;
    int CH = (((W + 3) / 4) + 255) & ~255;
    hist_all<<<CH / 256, 256>>>(edge_index, user_edge_index, mat_row, mat_col,
                                p_ce, p_rkg, p_cu, p_ru,
                                p_cur, p_rmr, p_cic, p_rmc,
                                E, UE, M, CH);

    // 3) merged offsets
    offsets_all<<<NB_E + NB_U + NB_IC + NB_UR, 256>>>(
        p_ce, p_oe, p_cu, p_ou, p_cic, p_oic, p_cur, p_our, p_cursor);

    // 4) merged fill (ILP x4)
    fill_all<<<CH / 256, 256>>>(edge_index, edge_type,
                                user_edge_index, user_edge_type,
                                mat_row, mat_col,
                                p_oe, p_rkg, p_be,
                                p_ou, p_ru, p_bu,
                                p_our, p_rmr, p_bur,
                                p_oic, p_rmc, p_bic,
                                E, UE, M, CH);

    // 5) merged gather (warp per row, writes means; zero-degree rows write 0)
    gather_all<<<(NROWS_ALL * 32 + 255) / 256, 256>>>(
        entity_emb, user_emb, weight,
        p_be, p_oe, p_ce,
        p_bu, p_ou, p_cu,
        p_bic, p_oic, p_cic,
        p_bur, p_our, p_cur,
        ent_out, usr_out, p_iu, p_ui);

    // 6) merged gated fusion
    fusion2<<<FUS_BLOCKS, 256>>>(
        ent_out, p_iu, gate1_w, gate2_w, ent_out, N_ITEMS,
        usr_out, p_ui, gate3_w, gate2_w, usr_out, N_USERS);
}